// round 3
// baseline (speedup 1.0000x reference)
#include <cuda_runtime.h>

#define NB 2
#define NT 2048
#define NE 1024
#define NH 16
#define ND 64
#define NK 1024

// Scratch (no allocation allowed in kernel_launch)
__device__ float g_q[NB*NH*NT*ND];
__device__ float g_k[NB*NH*NT*ND];
__device__ float g_v[NB*NH*NT*ND];
__device__ float g_o[(size_t)NB*NT*NE];

// ---------------------------------------------------------------------------
// GEMM 1: C[4096,3072] = X[4096,1024] @ W^T (W[3072,1024]) + bias
// Epilogue scatters into g_q/g_k/g_v laid out [B,H,T,D].
// 128x128x16 tile, 256 threads, 8x8 per-thread, stride-16 fragment mapping.
// ---------------------------------------------------------------------------
__global__ __launch_bounds__(256) void qkv_gemm_kernel(const float* __restrict__ X,
                                                       const float* __restrict__ W,
                                                       const float* __restrict__ bias) {
    __shared__ float As[16][128];
    __shared__ float Bs[16][128];
    const int tid = threadIdx.x;
    const int tx = tid & 15, ty = tid >> 4;
    const int row0 = blockIdx.y * 128;
    const int col0 = blockIdx.x * 128;

    float acc[8][8];
#pragma unroll
    for (int i = 0; i < 8; i++)
#pragma unroll
        for (int j = 0; j < 8; j++) acc[i][j] = 0.f;

    const int lr = tid >> 2;          // 0..63
    const int lk = (tid & 3) << 2;    // 0,4,8,12
    const float* xp = X + (size_t)(row0 + lr) * NK + lk;
    const float* wp = W + (size_t)(col0 + lr) * NK + lk;

    for (int k0 = 0; k0 < NK; k0 += 16) {
        float4 a0 = *(const float4*)(xp + k0);
        float4 a1 = *(const float4*)(xp + (size_t)64 * NK + k0);
        float4 b0 = *(const float4*)(wp + k0);
        float4 b1 = *(const float4*)(wp + (size_t)64 * NK + k0);
        As[lk+0][lr]    = a0.x; As[lk+1][lr]    = a0.y; As[lk+2][lr]    = a0.z; As[lk+3][lr]    = a0.w;
        As[lk+0][lr+64] = a1.x; As[lk+1][lr+64] = a1.y; As[lk+2][lr+64] = a1.z; As[lk+3][lr+64] = a1.w;
        Bs[lk+0][lr]    = b0.x; Bs[lk+1][lr]    = b0.y; Bs[lk+2][lr]    = b0.z; Bs[lk+3][lr]    = b0.w;
        Bs[lk+0][lr+64] = b1.x; Bs[lk+1][lr+64] = b1.y; Bs[lk+2][lr+64] = b1.z; Bs[lk+3][lr+64] = b1.w;
        __syncthreads();
#pragma unroll
        for (int kk = 0; kk < 16; kk++) {
            float af[8], bf[8];
#pragma unroll
            for (int i = 0; i < 8; i++) af[i] = As[kk][ty + 16*i];
#pragma unroll
            for (int j = 0; j < 8; j++) bf[j] = Bs[kk][tx + 16*j];
#pragma unroll
            for (int i = 0; i < 8; i++)
#pragma unroll
                for (int j = 0; j < 8; j++)
                    acc[i][j] = fmaf(af[i], bf[j], acc[i][j]);
        }
        __syncthreads();
    }

    // col0 is 128-aligned and 1024 % 128 == 0 -> 'which' is uniform per block
    const int which = col0 >> 10;
    float* dstbase = (which == 0) ? g_q : (which == 1 ? g_k : g_v);
#pragma unroll
    for (int j = 0; j < 8; j++) {
        const int col = col0 + tx + 16*j;
        const int e = col & (NE - 1);
        const int h = e >> 6;
        const int d = e & 63;
        const float bj = bias[col];
#pragma unroll
        for (int i = 0; i < 8; i++) {
            const int row = row0 + ty + 16*i;
            const int b = row >> 11;
            const int t = row & (NT - 1);
            dstbase[(((size_t)(b * NH + h)) * NT + t) * ND + d] = acc[i][j] + bj;
        }
    }
}

// ---------------------------------------------------------------------------
// Flash attention: one block = one (b,h) x 64-query tile. 256 threads.
// Qs/KP swizzled by (row & 31) for conflict-free strided reads.
// KP buffer is reused: K tile during S = Q K^T, then P = exp(S - m) for PV.
// ---------------------------------------------------------------------------
__global__ __launch_bounds__(256) void attn_kernel() {
    __shared__ float Qs[64][64];  // Qs[i][d ^ (i&31)]
    __shared__ float KP[64][64];  // K: KP[j][d ^ (j&31)]; then P: KP[i][k ^ (i&31)]
    __shared__ float Vs[64][64];  // Vs[k][d] plain

    const int tid = threadIdx.x;
    const int tx = tid & 15, ty = tid >> 4;
    const int bh = blockIdx.y;
    const int q0 = blockIdx.x * 64;

    const float* Qg = g_q + (size_t)bh * NT * ND;
    const float* Kg = g_k + (size_t)bh * NT * ND;
    const float* Vg = g_v + (size_t)bh * NT * ND;

    // Load Q tile (swizzled)
    for (int it = tid; it < 64 * 16; it += 256) {
        const int r = it >> 4;
        const int c = (it & 15) << 2;
        float4 v = *(const float4*)(Qg + (size_t)(q0 + r) * ND + c);
        const int s = r & 31;
        Qs[r][(c + 0) ^ s] = v.x; Qs[r][(c + 1) ^ s] = v.y;
        Qs[r][(c + 2) ^ s] = v.z; Qs[r][(c + 3) ^ s] = v.w;
    }

    float mrow[4], lrow[4], acc[4][4];
#pragma unroll
    for (int i = 0; i < 4; i++) {
        mrow[i] = -3.0e38f; lrow[i] = 0.f;
#pragma unroll
        for (int j = 0; j < 4; j++) acc[i][j] = 0.f;
    }
    __syncthreads();

    for (int k0 = 0; k0 < NT; k0 += 64) {
        // Load K (swizzled) and V (plain) tiles
        for (int it = tid; it < 64 * 16; it += 256) {
            const int r = it >> 4;
            const int c = (it & 15) << 2;
            float4 kv = *(const float4*)(Kg + (size_t)(k0 + r) * ND + c);
            const int s = r & 31;
            KP[r][(c + 0) ^ s] = kv.x; KP[r][(c + 1) ^ s] = kv.y;
            KP[r][(c + 2) ^ s] = kv.z; KP[r][(c + 3) ^ s] = kv.w;
            float4 vv = *(const float4*)(Vg + (size_t)(k0 + r) * ND + c);
            *(float4*)&Vs[r][c] = vv;
        }
        __syncthreads();

        // S = Q K^T : thread owns rows 4ty..4ty+3, cols tx+16j
        float sv[4][4];
#pragma unroll
        for (int i = 0; i < 4; i++)
#pragma unroll
            for (int j = 0; j < 4; j++) sv[i][j] = 0.f;

        for (int d = 0; d < 64; d++) {
            float qf[4], kf[4];
#pragma unroll
            for (int i = 0; i < 4; i++) {
                const int r = 4 * ty + i;
                qf[i] = Qs[r][d ^ (r & 31)];
            }
#pragma unroll
            for (int j = 0; j < 4; j++) {
                const int r = tx + 16 * j;
                kf[j] = KP[r][d ^ (r & 31)];
            }
#pragma unroll
            for (int i = 0; i < 4; i++)
#pragma unroll
                for (int j = 0; j < 4; j++)
                    sv[i][j] = fmaf(qf[i], kf[j], sv[i][j]);
        }

        // Online softmax (row reduction across the 16 tx lanes of a half-warp)
#pragma unroll
        for (int i = 0; i < 4; i++) {
            float mx = -3.0e38f;
#pragma unroll
            for (int j = 0; j < 4; j++) {
                sv[i][j] *= 0.125f;   // 1/sqrt(64)
                mx = fmaxf(mx, sv[i][j]);
            }
#pragma unroll
            for (int off = 8; off >= 1; off >>= 1)
                mx = fmaxf(mx, __shfl_xor_sync(0xffffffffu, mx, off));
            const float mnew = fmaxf(mrow[i], mx);
            const float corr = __expf(mrow[i] - mnew);
            float rs = 0.f;
#pragma unroll
            for (int j = 0; j < 4; j++) {
                sv[i][j] = __expf(sv[i][j] - mnew);
                rs += sv[i][j];
            }
#pragma unroll
            for (int off = 8; off >= 1; off >>= 1)
                rs += __shfl_xor_sync(0xffffffffu, rs, off);
            lrow[i] = lrow[i] * corr + rs;
            mrow[i] = mnew;
#pragma unroll
            for (int j = 0; j < 4; j++) acc[i][j] *= corr;
        }
        __syncthreads();   // everyone done reading K from KP

        // Write P into KP (row-swizzled)
#pragma unroll
        for (int i = 0; i < 4; i++) {
            const int r = 4 * ty + i;
            const int s = r & 31;
#pragma unroll
            for (int j = 0; j < 4; j++)
                KP[r][(tx + 16 * j) ^ s] = sv[i][j];
        }
        __syncthreads();

        // O += P @ V : thread owns O rows 4ty..4ty+3, d cols tx+16j
        for (int k = 0; k < 64; k++) {
            float pf[4], vf[4];
#pragma unroll
            for (int i = 0; i < 4; i++) {
                const int r = 4 * ty + i;
                pf[i] = KP[r][k ^ (r & 31)];
            }
#pragma unroll
            for (int j = 0; j < 4; j++)
                vf[j] = Vs[k][tx + 16 * j];
#pragma unroll
            for (int i = 0; i < 4; i++)
#pragma unroll
                for (int j = 0; j < 4; j++)
                    acc[i][j] = fmaf(pf[i], vf[j], acc[i][j]);
        }
        __syncthreads();   // before next tile overwrites KP/Vs
    }

    // Epilogue: write [B,T,E] so the output projection is a plain GEMM
    const int b = bh >> 4;
    const int h = bh & 15;
#pragma unroll
    for (int i = 0; i < 4; i++) {
        const float inv = 1.f / lrow[i];
        const int t = q0 + 4 * ty + i;
#pragma unroll
        for (int j = 0; j < 4; j++) {
            const int d = tx + 16 * j;
            g_o[((size_t)(b * NT + t)) * NE + h * ND + d] = acc[i][j] * inv;
        }
    }
}

// ---------------------------------------------------------------------------
// GEMM 2: out[4096,1024] = g_o @ out_w^T + out_b
// ---------------------------------------------------------------------------
__global__ __launch_bounds__(256) void out_gemm_kernel(const float* __restrict__ W,
                                                       const float* __restrict__ bias,
                                                       float* __restrict__ out) {
    __shared__ float As[16][128];
    __shared__ float Bs[16][128];
    const int tid = threadIdx.x;
    const int tx = tid & 15, ty = tid >> 4;
    const int row0 = blockIdx.y * 128;
    const int col0 = blockIdx.x * 128;

    float acc[8][8];
#pragma unroll
    for (int i = 0; i < 8; i++)
#pragma unroll
        for (int j = 0; j < 8; j++) acc[i][j] = 0.f;

    const int lr = tid >> 2;
    const int lk = (tid & 3) << 2;
    const float* xp = g_o + (size_t)(row0 + lr) * NK + lk;
    const float* wp = W + (size_t)(col0 + lr) * NK + lk;

    for (int k0 = 0; k0 < NK; k0 += 16) {
        float4 a0 = *(const float4*)(xp + k0);
        float4 a1 = *(const float4*)(xp + (size_t)64 * NK + k0);
        float4 b0 = *(const float4*)(wp + k0);
        float4 b1 = *(const float4*)(wp + (size_t)64 * NK + k0);
        As[lk+0][lr]    = a0.x; As[lk+1][lr]    = a0.y; As[lk+2][lr]    = a0.z; As[lk+3][lr]    = a0.w;
        As[lk+0][lr+64] = a1.x; As[lk+1][lr+64] = a1.y; As[lk+2][lr+64] = a1.z; As[lk+3][lr+64] = a1.w;
        Bs[lk+0][lr]    = b0.x; Bs[lk+1][lr]    = b0.y; Bs[lk+2][lr]    = b0.z; Bs[lk+3][lr]    = b0.w;
        Bs[lk+0][lr+64] = b1.x; Bs[lk+1][lr+64] = b1.y; Bs[lk+2][lr+64] = b1.z; Bs[lk+3][lr+64] = b1.w;
        __syncthreads();
#pragma unroll
        for (int kk = 0; kk < 16; kk++) {
            float af[8], bf[8];
#pragma unroll
            for (int i = 0; i < 8; i++) af[i] = As[kk][ty + 16*i];
#pragma unroll
            for (int j = 0; j < 8; j++) bf[j] = Bs[kk][tx + 16*j];
#pragma unroll
            for (int i = 0; i < 8; i++)
#pragma unroll
                for (int j = 0; j < 8; j++)
                    acc[i][j] = fmaf(af[i], bf[j], acc[i][j]);
        }
        __syncthreads();
    }

#pragma unroll
    for (int j = 0; j < 8; j++) {
        const int col = col0 + tx + 16*j;
        const float bj = bias[col];
#pragma unroll
        for (int i = 0; i < 8; i++) {
            const int row = row0 + ty + 16*i;
            out[(size_t)row * NE + col] = acc[i][j] + bj;
        }
    }
}

// ---------------------------------------------------------------------------
extern "C" void kernel_launch(void* const* d_in, const int* in_sizes, int n_in,
                              void* d_out, int out_size) {
    const float* x     = (const float*)d_in[0];  // [2,2048,1024]
    const float* qkv_w = (const float*)d_in[1];  // [3072,1024]
    const float* qkv_b = (const float*)d_in[2];  // [3072]
    const float* out_w = (const float*)d_in[3];  // [1024,1024]
    const float* out_b = (const float*)d_in[4];  // [1024]
    float* out = (float*)d_out;                  // [2,2048,1024]

    dim3 g1(3 * NE / 128, NB * NT / 128);   // (24, 32)
    qkv_gemm_kernel<<<g1, 256>>>(x, qkv_w, qkv_b);

    dim3 ga(NT / 64, NB * NH);              // (32, 32)
    attn_kernel<<<ga, 256>>>();

    dim3 g2(NE / 128, NB * NT / 128);       // (8, 32)
    out_gemm_kernel<<<g2, 256>>>(out_w, out_b, out);
}